// round 4
// baseline (speedup 1.0000x reference)
#include <cuda_runtime.h>
#include <math.h>

// ---------------- problem constants ----------------
#define BB   2
#define NN   512
#define HIDD 768
#define BIAF 256
#define DD   257      // BIAF + 1
#define DP   272      // DD padded to multiple of 16
#define CLSK 14
#define HSZ  539      // 2*(BIAF+1) + 25
#define NPOS 30
#define SDIM 25

// ---------------- device scratch ----------------
__device__ float g_h1[BB * NN * DP];                   // tf32-rounded gelu(x@mlp1)+1, zero pad
__device__ float g_t1[BB * NN * DP];
__device__ float g_head1[BB * NN * DD];                // full precision (for bias dots)
__device__ float g_tail1[BB * NN * DD];
__device__ float g_u[BB * CLSK * NN * DP];             // tf32-rounded h1 @ biaf_W[k]
__device__ float g_bwT[CLSK * DP * DP + 64 * DP];      // tf32-rounded biaf_W[k]^T [n][i], zero pad + tile slack
__device__ float g_headW[BB * CLSK * NN];
__device__ float g_tailW[BB * CLSK * NN];
__device__ float g_sbias[CLSK * NPOS];

// ---------------- helpers ----------------
__device__ __forceinline__ unsigned f2t(float f) {
    unsigned u; asm("cvt.rna.tf32.f32 %0, %1;" : "=r"(u) : "f"(f)); return u;
}
__device__ __forceinline__ float f2tf(float f) { unsigned u = f2t(f); return __uint_as_float(u); }
__device__ __forceinline__ void mma8(float c[4], const unsigned a[4], const unsigned b[2]) {
    asm volatile("mma.sync.aligned.m16n8k8.row.col.f32.tf32.tf32.f32 "
                 "{%0,%1,%2,%3}, {%4,%5,%6,%7}, {%8,%9}, {%0,%1,%2,%3};"
                 : "+f"(c[0]), "+f"(c[1]), "+f"(c[2]), "+f"(c[3])
                 : "r"(a[0]), "r"(a[1]), "r"(a[2]), "r"(a[3]), "r"(b[0]), "r"(b[1]));
}
__device__ __forceinline__ void cp16(void* dst, const void* src) {
    unsigned d = (unsigned)__cvta_generic_to_shared(dst);
    asm volatile("cp.async.ca.shared.global [%0], [%1], 16;" :: "r"(d), "l"(src));
}
#define CP_COMMIT() asm volatile("cp.async.commit_group;")
#define CP_WAIT(n)  asm volatile("cp.async.wait_group %0;" :: "n"(n))

// ---------------- transpose biaf_W -> g_bwT [k][j][i], tf32-rounded ----------------
__global__ void tr_kernel(const float* __restrict__ bw)
{
    __shared__ float tile[32][33];
    int k = blockIdx.z;
    int i0 = blockIdx.x * 32, j0 = blockIdx.y * 32;
    int tx = threadIdx.x, ty = threadIdx.y;
    #pragma unroll
    for (int r = 0; r < 4; r++) {
        int i = i0 + ty + r * 8, j = j0 + tx;
        tile[ty + r * 8][tx] = (i < DD && j < DD) ? bw[(k * DD + i) * DD + j] : 0.0f;
    }
    __syncthreads();
    #pragma unroll
    for (int r = 0; r < 4; r++) {
        int j = j0 + ty + r * 8, i = i0 + tx;
        if (j < DP && i < DP) g_bwT[(k * DP + j) * DP + i] = f2tf(tile[tx][ty + r * 8]);
    }
}

// ---------------- stage 1: projections via tf32 mma. 64x64 tiles, 128 thr ----------------
__global__ void proj_kernel(const float* __restrict__ x, const float* __restrict__ y,
                            const float* __restrict__ w1, const float* __restrict__ b1,
                            const float* __restrict__ w2, const float* __restrict__ b2,
                            const float* __restrict__ hw, const float* __restrict__ hb,
                            const float* __restrict__ tw, const float* __restrict__ tb)
{
    __shared__ unsigned As[64][20];
    __shared__ unsigned Bs[64][20];

    const int v = blockIdx.z;
    const float* X = (v == 1) ? y : x;
    const float* Wm; const float* bias;
    if (v == 0)      { Wm = w1; bias = b1; }
    else if (v == 1) { Wm = w2; bias = b2; }
    else if (v == 2) { Wm = hw; bias = hb; }
    else             { Wm = tw; bias = tb; }

    const int m0 = blockIdx.x * 64;
    const int n0 = blockIdx.y * 64;
    const int tid = threadIdx.x;
    const int w = tid >> 5, lane = tid & 31, g = lane >> 2, tig = lane & 3;
    const int wm = (w >> 1) * 32, wn = (w & 1) * 32;

    float acc[2][4][4] = {};
    float4 na, nb;
    {
        int f = tid, r = f >> 1, kq = (f & 1) * 8;
        na = *(const float4*)&X[(m0 + r) * HIDD + kq];
        nb = *(const float4*)&Wm[(n0 + r) * HIDD + kq];
    }

    for (int k0 = 0; k0 < HIDD; k0 += 16) {
        int f = tid, r = f >> 1, kq = (f & 1) * 8;
        float4 na2 = *(const float4*)&X[(m0 + r) * HIDD + k0 + kq + 4];
        float4 nb2 = *(const float4*)&Wm[(n0 + r) * HIDD + k0 + kq + 4];
        unsigned* da = &As[r][kq];
        da[0] = f2t(na.x); da[1] = f2t(na.y); da[2] = f2t(na.z); da[3] = f2t(na.w);
        da[4] = f2t(na2.x); da[5] = f2t(na2.y); da[6] = f2t(na2.z); da[7] = f2t(na2.w);
        unsigned* db = &Bs[r][kq];
        db[0] = f2t(nb.x); db[1] = f2t(nb.y); db[2] = f2t(nb.z); db[3] = f2t(nb.w);
        db[4] = f2t(nb2.x); db[5] = f2t(nb2.y); db[6] = f2t(nb2.z); db[7] = f2t(nb2.w);
        __syncthreads();
        if (k0 + 16 < HIDD) {
            na = *(const float4*)&X[(m0 + r) * HIDD + k0 + 16 + kq];
            nb = *(const float4*)&Wm[(n0 + r) * HIDD + k0 + 16 + kq];
        }
        #pragma unroll
        for (int kk = 0; kk < 2; kk++) {
            unsigned a[2][4], b[4][2];
            #pragma unroll
            for (int i = 0; i < 2; i++) {
                a[i][0] = As[wm + i * 16 + g][kk * 8 + tig];
                a[i][1] = As[wm + i * 16 + g + 8][kk * 8 + tig];
                a[i][2] = As[wm + i * 16 + g][kk * 8 + tig + 4];
                a[i][3] = As[wm + i * 16 + g + 8][kk * 8 + tig + 4];
            }
            #pragma unroll
            for (int j = 0; j < 4; j++) {
                b[j][0] = Bs[wn + j * 8 + g][kk * 8 + tig];
                b[j][1] = Bs[wn + j * 8 + g][kk * 8 + tig + 4];
            }
            #pragma unroll
            for (int i = 0; i < 2; i++)
                #pragma unroll
                for (int j = 0; j < 4; j++) mma8(acc[i][j], a[i], b[j]);
        }
        __syncthreads();
    }

    #pragma unroll
    for (int i = 0; i < 2; i++) {
        #pragma unroll
        for (int rh = 0; rh < 2; rh++) {
            int m = m0 + wm + i * 16 + g + rh * 8;
            #pragma unroll
            for (int j = 0; j < 4; j++) {
                #pragma unroll
                for (int cb = 0; cb < 2; cb++) {
                    int c = n0 + wn + j * 8 + tig * 2 + cb;
                    float vv = acc[i][j][rh * 2 + cb] + bias[c];
                    if (v < 2) {
                        vv = 0.5f * vv * (1.0f + erff(vv * 0.70710678118654752f));
                        float* dst = (v == 0) ? g_h1 : g_t1;
                        dst[m * DP + c] = f2tf(vv);
                    } else {
                        vv = (vv > 0.0f) ? vv : 0.01f * vv;
                        float* dst = (v == 2) ? g_head1 : g_tail1;
                        dst[m * DD + c] = vv;
                    }
                }
            }
        }
    }
}

// ---------------- stage 2: pad / ones ----------------
__global__ void pad_kernel()
{
    int bm = blockIdx.x * blockDim.x + threadIdx.x;
    if (bm >= BB * NN) return;
    g_h1[bm * DP + 256] = 1.0f;
    g_t1[bm * DP + 256] = 1.0f;
    #pragma unroll
    for (int j = 257; j < DP; j++) { g_h1[bm * DP + j] = 0.0f; g_t1[bm * DP + j] = 0.0f; }
    g_head1[bm * DD + 256] = 1.0f;
    g_tail1[bm * DD + 256] = 1.0f;
}

// ---------------- stage 3: rank-1 bias precomputes (warp per row, all 14 classes in flight) ----------------
__global__ void hw_kernel(const float* __restrict__ W)
{
    int warp_id = (blockIdx.x * blockDim.x + threadIdx.x) >> 5;
    int lane = threadIdx.x & 31;
    if (warp_id >= 2 * BB * NN) return;
    int which = (warp_id >= BB * NN) ? 1 : 0;
    int bm = warp_id - which * BB * NN;            // b*NN + m
    const float* hr = (which ? g_tail1 : g_head1) + bm * DD;

    float h[9];
    #pragma unroll
    for (int s = 0; s < 9; s++) {
        int i = lane + 32 * s;
        h[s] = (i < DD) ? hr[i] : 0.0f;
    }

    const float* Wb = W + which * DD;
    float acc[CLSK];
    #pragma unroll
    for (int k = 0; k < CLSK; k++) acc[k] = 0.0f;

    #pragma unroll
    for (int sg = 0; sg < 9; sg++) {
        int i = lane + 32 * sg;
        if (i < DD) {
            float hv = h[sg];
            #pragma unroll
            for (int k = 0; k < CLSK; k++)
                acc[k] += hv * __ldg(&Wb[k * HSZ + i]);
        }
    }

    // 14 independent butterfly chains
    #pragma unroll
    for (int k = 0; k < CLSK; k++) {
        #pragma unroll
        for (int o = 16; o; o >>= 1) acc[k] += __shfl_xor_sync(0xffffffffu, acc[k], o);
    }

    if (lane == 0) {
        float* dst = which ? g_tailW : g_headW;
        int b = bm / NN, m = bm % NN;
        #pragma unroll
        for (int k = 0; k < CLSK; k++)
            dst[(b * CLSK + k) * NN + m] = acc[k];
    }
}

__global__ void sb_kernel(const float* __restrict__ W, const float* __restrict__ se)
{
    int idx = threadIdx.x;
    if (idx >= CLSK * NPOS) return;
    int k = idx / NPOS, p = idx % NPOS;
    float s = 0.0f;
    #pragma unroll
    for (int d = 0; d < SDIM; d++) s += se[p * SDIM + d] * W[k * HSZ + 2 * DD + d];
    g_sbias[idx] = s;
}

// ---------------- stage 4: u = h1 @ bwT^T. 64x64 tiles, 128 thr, 3-stage cp.async, 1 sync/iter ----------------
__global__ void u_kernel()
{
    __shared__ unsigned As[3][64][20];
    __shared__ unsigned Bs[3][64][20];

    const int bk = blockIdx.z;
    const int b = bk / CLSK, kcls = bk % CLSK;
    const int m0 = blockIdx.x * 64;
    const int n0 = blockIdx.y * 64;
    const float* A  = g_h1 + b * NN * DP;
    const float* Bm = g_bwT + kcls * DP * DP;
    const int tid = threadIdx.x;
    const int w = tid >> 5, lane = tid & 31, g = lane >> 2, tig = lane & 3;
    const int wm = (w >> 1) * 32, wn = (w & 1) * 32;

    float acc[2][4][4] = {};

    #define U_STAGE(buf, k0)                                                     \
        do { _Pragma("unroll")                                                   \
        for (int h = 0; h < 2; h++) {                                            \
            int f = tid + h * 128;                                               \
            int r = f >> 2, kq = (f & 3) * 4;                                    \
            cp16(&As[buf][r][kq], &A[(m0 + r) * DP + (k0) + kq]);                \
            cp16(&Bs[buf][r][kq], &Bm[(n0 + r) * DP + (k0) + kq]);               \
        } } while (0)

    U_STAGE(0, 0);  CP_COMMIT();
    U_STAGE(1, 16); CP_COMMIT();

    const int NT = DP / 16;  // 17
    int cur = 0;
    for (int kt = 0; kt < NT; kt++) {
        if (kt + 1 < NT) CP_WAIT(1); else CP_WAIT(0);
        __syncthreads();
        if (kt + 2 < NT) {
            int nxt = cur + 2; if (nxt >= 3) nxt -= 3;
            U_STAGE(nxt, (kt + 2) * 16);
            CP_COMMIT();
        }
        #pragma unroll
        for (int kk = 0; kk < 2; kk++) {
            unsigned a[2][4], b2[4][2];
            #pragma unroll
            for (int i = 0; i < 2; i++) {
                a[i][0] = As[cur][wm + i * 16 + g][kk * 8 + tig];
                a[i][1] = As[cur][wm + i * 16 + g + 8][kk * 8 + tig];
                a[i][2] = As[cur][wm + i * 16 + g][kk * 8 + tig + 4];
                a[i][3] = As[cur][wm + i * 16 + g + 8][kk * 8 + tig + 4];
            }
            #pragma unroll
            for (int j = 0; j < 4; j++) {
                b2[j][0] = Bs[cur][wn + j * 8 + g][kk * 8 + tig];
                b2[j][1] = Bs[cur][wn + j * 8 + g][kk * 8 + tig + 4];
            }
            #pragma unroll
            for (int i = 0; i < 2; i++)
                #pragma unroll
                for (int j = 0; j < 4; j++) mma8(acc[i][j], a[i], b2[j]);
        }
        if (++cur == 3) cur = 0;
    }

    float* U = g_u + bk * NN * DP;
    #pragma unroll
    for (int i = 0; i < 2; i++) {
        #pragma unroll
        for (int rh = 0; rh < 2; rh++) {
            int m = m0 + wm + i * 16 + g + rh * 8;
            #pragma unroll
            for (int j = 0; j < 4; j++) {
                int c = n0 + wn + j * 8 + tig * 2;
                if (c + 1 < DP) {
                    float2 vv = make_float2(f2tf(acc[i][j][rh * 2 + 0]),
                                            f2tf(acc[i][j][rh * 2 + 1]));
                    *(float2*)&U[m * DP + c] = vv;
                }
            }
        }
    }
}

// ---------------- stage 5: out = u @ t1^T + biases. 128x128 tiles, 256 thr, 3-stage cp.async ----------------
#define O_TILE_U (128 * 20)
__global__ void out_kernel(float* __restrict__ out)
{
    extern __shared__ unsigned dyn[];
    unsigned (*As)[128][20] = (unsigned(*)[128][20])dyn;
    unsigned (*Bs)[128][20] = (unsigned(*)[128][20])(dyn + 3 * O_TILE_U);
    __shared__ float sHW[128], sTW[128], sSB[NPOS];

    const int bk = blockIdx.z;
    const int b = bk / CLSK, kcls = bk % CLSK;
    const int m0 = blockIdx.x * 128;
    const int n0 = blockIdx.y * 128;
    const float* A  = g_u + bk * NN * DP;
    const float* Bt = g_t1 + b * NN * DP;
    const int tid = threadIdx.x;
    const int w = tid >> 5, lane = tid & 31, g = lane >> 2, tig = lane & 3;
    const int wm = (w >> 1) * 32, wn = (w & 1) * 64;

    if (tid < 128) {
        sHW[tid] = g_headW[bk * NN + m0 + tid];
        sTW[tid] = g_tailW[bk * NN + n0 + tid];
    }
    if (tid < NPOS) sSB[tid] = g_sbias[kcls * NPOS + tid];

    float acc[2][8][4] = {};

    #define O_STAGE(buf, k0)                                                     \
        do { _Pragma("unroll")                                                   \
        for (int h = 0; h < 2; h++) {                                            \
            int f = tid + h * 256;                                               \
            int r = f >> 2, kq = (f & 3) * 4;                                    \
            cp16(&As[buf][r][kq], &A[(m0 + r) * DP + (k0) + kq]);                \
            cp16(&Bs[buf][r][kq], &Bt[(n0 + r) * DP + (k0) + kq]);               \
        } } while (0)

    O_STAGE(0, 0);  CP_COMMIT();
    O_STAGE(1, 16); CP_COMMIT();

    const int NT = DP / 16;  // 17
    int cur = 0;
    for (int kt = 0; kt < NT; kt++) {
        if (kt + 1 < NT) CP_WAIT(1); else CP_WAIT(0);
        __syncthreads();
        if (kt + 2 < NT) {
            int nxt = cur + 2; if (nxt >= 3) nxt -= 3;
            O_STAGE(nxt, (kt + 2) * 16);
            CP_COMMIT();
        }
        #pragma unroll
        for (int kk = 0; kk < 2; kk++) {
            unsigned a[2][4], b2[8][2];
            #pragma unroll
            for (int i = 0; i < 2; i++) {
                a[i][0] = As[cur][wm + i * 16 + g][kk * 8 + tig];
                a[i][1] = As[cur][wm + i * 16 + g + 8][kk * 8 + tig];
                a[i][2] = As[cur][wm + i * 16 + g][kk * 8 + tig + 4];
                a[i][3] = As[cur][wm + i * 16 + g + 8][kk * 8 + tig + 4];
            }
            #pragma unroll
            for (int j = 0; j < 8; j++) {
                b2[j][0] = Bs[cur][wn + j * 8 + g][kk * 8 + tig];
                b2[j][1] = Bs[cur][wn + j * 8 + g][kk * 8 + tig + 4];
            }
            #pragma unroll
            for (int i = 0; i < 2; i++)
                #pragma unroll
                for (int j = 0; j < 8; j++) mma8(acc[i][j], a[i], b2[j]);
        }
        if (++cur == 3) cur = 0;
    }

    #pragma unroll
    for (int i = 0; i < 2; i++) {
        #pragma unroll
        for (int rh = 0; rh < 2; rh++) {
            int ml = wm + i * 16 + g + rh * 8;
            int m = m0 + ml;
            float hv = sHW[ml];
            #pragma unroll
            for (int j = 0; j < 8; j++) {
                int cl = wn + j * 8 + tig * 2;
                int n = n0 + cl;
                int d0 = n - m;     d0 = (d0 < -15) ? -15 : (d0 > 14 ? 14 : d0);
                int d1 = n + 1 - m; d1 = (d1 < -15) ? -15 : (d1 > 14 ? 14 : d1);
                float2 vv;
                vv.x = acc[i][j][rh * 2 + 0] + hv + sTW[cl]     + sSB[d0 + 15];
                vv.y = acc[i][j][rh * 2 + 1] + hv + sTW[cl + 1] + sSB[d1 + 15];
                *(float2*)&out[(bk * NN + m) * NN + n] = vv;
            }
        }
    }
}

// ---------------- launch ----------------
extern "C" void kernel_launch(void* const* d_in, const int* in_sizes, int n_in,
                              void* d_out, int out_size)
{
    const float* x   = (const float*)d_in[0];
    const float* y   = (const float*)d_in[1];
    // d_in[2] = z : dead input
    const float* w1  = (const float*)d_in[3];
    const float* b1  = (const float*)d_in[4];
    const float* w2  = (const float*)d_in[5];
    const float* b2  = (const float*)d_in[6];
    const float* hw  = (const float*)d_in[7];
    const float* hb  = (const float*)d_in[8];
    const float* tw  = (const float*)d_in[9];
    const float* tb  = (const float*)d_in[10];
    const float* bw  = (const float*)d_in[11];
    const float* W   = (const float*)d_in[12];
    const float* se  = (const float*)d_in[13];
    float* out = (float*)d_out;

    const int OUT_SMEM = 3 * 2 * O_TILE_U * 4;   // 61440 bytes
    static int attr_done = 0;
    if (!attr_done) {
        cudaFuncSetAttribute(out_kernel, cudaFuncAttributeMaxDynamicSharedMemorySize, OUT_SMEM);
        attr_done = 1;
    }

    tr_kernel<<<dim3(9, 9, CLSK), dim3(32, 8)>>>(bw);
    proj_kernel<<<dim3(16, 4, 4), 128>>>(x, y, w1, b1, w2, b2, hw, hb, tw, tb);
    pad_kernel<<<4, 256>>>();
    hw_kernel<<<256, 256>>>(W);
    sb_kernel<<<1, 512>>>(W, se);
    u_kernel<<<dim3(8, 5, BB * CLSK), 128>>>();
    out_kernel<<<dim3(4, 4, BB * CLSK), 256, OUT_SMEM>>>(out);
}

// round 6
// speedup vs baseline: 1.0445x; 1.0445x over previous
#include <cuda_runtime.h>
#include <math.h>

// ---------------- problem constants ----------------
#define BB   2
#define NN   512
#define HIDD 768
#define BIAF 256
#define DD   257      // BIAF + 1
#define DP   272      // DD padded to multiple of 16
#define CLSK 14
#define HSZ  539      // 2*(BIAF+1) + 25
#define NPOS 30
#define SDIM 25

// ---------------- device scratch ----------------
__device__ float g_h1[BB * NN * DP];                   // tf32-rounded gelu(x@mlp1)+1, zero pad
__device__ float g_t1[BB * NN * DP];
__device__ float g_head1[BB * NN * DD];                // full precision (for bias dots)
__device__ float g_tail1[BB * NN * DD];
__device__ float g_u[BB * CLSK * NN * DP];             // tf32-rounded h1 @ biaf_W[k]
__device__ float g_bwT[CLSK * DP * DP + 64 * DP];      // tf32-rounded biaf_W[k]^T [n][i], zero pad + slack
__device__ float g_headW[BB * CLSK * NN];
__device__ float g_tailW[BB * CLSK * NN];
__device__ float g_sbias[CLSK * NPOS];

// ---------------- helpers ----------------
__device__ __forceinline__ unsigned f2t(float f) {
    unsigned u; asm("cvt.rna.tf32.f32 %0, %1;" : "=r"(u) : "f"(f)); return u;
}
__device__ __forceinline__ float f2tf(float f) { unsigned u = f2t(f); return __uint_as_float(u); }
__device__ __forceinline__ void mma8(float c[4], const unsigned a[4], const unsigned b[2]) {
    asm volatile("mma.sync.aligned.m16n8k8.row.col.f32.tf32.tf32.f32 "
                 "{%0,%1,%2,%3}, {%4,%5,%6,%7}, {%8,%9}, {%0,%1,%2,%3};"
                 : "+f"(c[0]), "+f"(c[1]), "+f"(c[2]), "+f"(c[3])
                 : "r"(a[0]), "r"(a[1]), "r"(a[2]), "r"(a[3]), "r"(b[0]), "r"(b[1]));
}
__device__ __forceinline__ void cp16(void* dst, const void* src) {
    unsigned d = (unsigned)__cvta_generic_to_shared(dst);
    asm volatile("cp.async.ca.shared.global [%0], [%1], 16;" :: "r"(d), "l"(src));
}
#define CP_COMMIT() asm volatile("cp.async.commit_group;")
#define CP_WAIT(n)  asm volatile("cp.async.wait_group %0;" :: "n"(n))

// ---------------- prep: fused transpose(biaf_W) + pad/ones + size-bias ----------------
// blocks [0, 1134): tr; [1134, 1138): pad; 1138: sb
#define TR_BLOCKS (9 * 9 * CLSK)
__global__ void prep_kernel(const float* __restrict__ bw, const float* __restrict__ W,
                            const float* __restrict__ se)
{
    int bi = blockIdx.x;
    int tid = threadIdx.x;

    if (bi < TR_BLOCKS) {
        __shared__ float tile[32][33];
        int k = bi / 81;
        int rem = bi % 81;
        int i0 = (rem / 9) * 32, j0 = (rem % 9) * 32;
        int tx = tid & 31, ty = tid >> 5;
        #pragma unroll
        for (int r = 0; r < 4; r++) {
            int i = i0 + ty + r * 8, j = j0 + tx;
            tile[ty + r * 8][tx] = (i < DD && j < DD) ? bw[(k * DD + i) * DD + j] : 0.0f;
        }
        __syncthreads();
        #pragma unroll
        for (int r = 0; r < 4; r++) {
            int j = j0 + ty + r * 8, i = i0 + tx;
            if (j < DP && i < DP) g_bwT[(k * DP + j) * DP + i] = f2tf(tile[tx][ty + r * 8]);
        }
        return;
    }

    if (bi < TR_BLOCKS + 4) {
        int bm = (bi - TR_BLOCKS) * 256 + tid;
        if (bm < BB * NN) {
            g_h1[bm * DP + 256] = 1.0f;
            g_t1[bm * DP + 256] = 1.0f;
            #pragma unroll
            for (int j = 257; j < DP; j++) { g_h1[bm * DP + j] = 0.0f; g_t1[bm * DP + j] = 0.0f; }
            g_head1[bm * DD + 256] = 1.0f;
            g_tail1[bm * DD + 256] = 1.0f;
        }
        return;
    }

    // sb: CLSK*NPOS = 420 entries, 256 threads -> strided loop (R5 bug fixed)
    for (int idx = tid; idx < CLSK * NPOS; idx += 256) {
        int k = idx / NPOS, p = idx % NPOS;
        float s = 0.0f;
        #pragma unroll
        for (int d = 0; d < SDIM; d++) s += se[p * SDIM + d] * W[k * HSZ + 2 * DD + d];
        g_sbias[idx] = s;
    }
}

// ---------------- stage 1: projections via tf32 mma. 64x64 tiles, 128 thr ----------------
__global__ void proj_kernel(const float* __restrict__ x, const float* __restrict__ y,
                            const float* __restrict__ w1, const float* __restrict__ b1,
                            const float* __restrict__ w2, const float* __restrict__ b2,
                            const float* __restrict__ hw, const float* __restrict__ hb,
                            const float* __restrict__ tw, const float* __restrict__ tb)
{
    __shared__ unsigned As[64][20];
    __shared__ unsigned Bs[64][20];

    const int v = blockIdx.z;
    const float* X = (v == 1) ? y : x;
    const float* Wm; const float* bias;
    if (v == 0)      { Wm = w1; bias = b1; }
    else if (v == 1) { Wm = w2; bias = b2; }
    else if (v == 2) { Wm = hw; bias = hb; }
    else             { Wm = tw; bias = tb; }

    const int m0 = blockIdx.x * 64;
    const int n0 = blockIdx.y * 64;
    const int tid = threadIdx.x;
    const int w = tid >> 5, lane = tid & 31, g = lane >> 2, tig = lane & 3;
    const int wm = (w >> 1) * 32, wn = (w & 1) * 32;

    float acc[2][4][4] = {};
    float4 na, nb;
    {
        int f = tid, r = f >> 1, kq = (f & 1) * 8;
        na = *(const float4*)&X[(m0 + r) * HIDD + kq];
        nb = *(const float4*)&Wm[(n0 + r) * HIDD + kq];
    }

    for (int k0 = 0; k0 < HIDD; k0 += 16) {
        int f = tid, r = f >> 1, kq = (f & 1) * 8;
        float4 na2 = *(const float4*)&X[(m0 + r) * HIDD + k0 + kq + 4];
        float4 nb2 = *(const float4*)&Wm[(n0 + r) * HIDD + k0 + kq + 4];
        unsigned* da = &As[r][kq];
        da[0] = f2t(na.x); da[1] = f2t(na.y); da[2] = f2t(na.z); da[3] = f2t(na.w);
        da[4] = f2t(na2.x); da[5] = f2t(na2.y); da[6] = f2t(na2.z); da[7] = f2t(na2.w);
        unsigned* db = &Bs[r][kq];
        db[0] = f2t(nb.x); db[1] = f2t(nb.y); db[2] = f2t(nb.z); db[3] = f2t(nb.w);
        db[4] = f2t(nb2.x); db[5] = f2t(nb2.y); db[6] = f2t(nb2.z); db[7] = f2t(nb2.w);
        __syncthreads();
        if (k0 + 16 < HIDD) {
            na = *(const float4*)&X[(m0 + r) * HIDD + k0 + 16 + kq];
            nb = *(const float4*)&Wm[(n0 + r) * HIDD + k0 + 16 + kq];
        }
        #pragma unroll
        for (int kk = 0; kk < 2; kk++) {
            unsigned a[2][4], b[4][2];
            #pragma unroll
            for (int i = 0; i < 2; i++) {
                a[i][0] = As[wm + i * 16 + g][kk * 8 + tig];
                a[i][1] = As[wm + i * 16 + g + 8][kk * 8 + tig];
                a[i][2] = As[wm + i * 16 + g][kk * 8 + tig + 4];
                a[i][3] = As[wm + i * 16 + g + 8][kk * 8 + tig + 4];
            }
            #pragma unroll
            for (int j = 0; j < 4; j++) {
                b[j][0] = Bs[wn + j * 8 + g][kk * 8 + tig];
                b[j][1] = Bs[wn + j * 8 + g][kk * 8 + tig + 4];
            }
            #pragma unroll
            for (int i = 0; i < 2; i++)
                #pragma unroll
                for (int j = 0; j < 4; j++) mma8(acc[i][j], a[i], b[j]);
        }
        __syncthreads();
    }

    #pragma unroll
    for (int i = 0; i < 2; i++) {
        #pragma unroll
        for (int rh = 0; rh < 2; rh++) {
            int m = m0 + wm + i * 16 + g + rh * 8;
            #pragma unroll
            for (int j = 0; j < 4; j++) {
                #pragma unroll
                for (int cb = 0; cb < 2; cb++) {
                    int c = n0 + wn + j * 8 + tig * 2 + cb;
                    float vv = acc[i][j][rh * 2 + cb] + bias[c];
                    if (v < 2) {
                        vv = 0.5f * vv * (1.0f + erff(vv * 0.70710678118654752f));
                        float* dst = (v == 0) ? g_h1 : g_t1;
                        dst[m * DP + c] = f2tf(vv);
                    } else {
                        vv = (vv > 0.0f) ? vv : 0.01f * vv;
                        float* dst = (v == 2) ? g_head1 : g_tail1;
                        dst[m * DD + c] = vv;
                    }
                }
            }
        }
    }
}

// ---------------- stage 3: rank-1 bias precomputes (warp per row, 2 passes of 7 classes) ----------------
__global__ void hw_kernel(const float* __restrict__ W)
{
    int warp_id = (blockIdx.x * blockDim.x + threadIdx.x) >> 5;
    int lane = threadIdx.x & 31;
    if (warp_id >= 2 * BB * NN) return;
    int which = (warp_id >= BB * NN) ? 1 : 0;
    int bm = warp_id - which * BB * NN;            // b*NN + m
    const float* hr = (which ? g_tail1 : g_head1) + bm * DD;

    float h[9];
    #pragma unroll
    for (int s = 0; s < 9; s++) {
        int i = lane + 32 * s;
        h[s] = (i < DD) ? hr[i] : 0.0f;
    }

    const float* Wb = W + which * DD;
    float* dst = which ? g_tailW : g_headW;
    int b = bm / NN, m = bm % NN;

    #pragma unroll
    for (int half = 0; half < 2; half++) {
        float acc[7];
        #pragma unroll
        for (int k = 0; k < 7; k++) acc[k] = 0.0f;
        #pragma unroll
        for (int sg = 0; sg < 9; sg++) {
            int i = lane + 32 * sg;
            if (i < DD) {
                float hv = h[sg];
                #pragma unroll
                for (int k = 0; k < 7; k++)
                    acc[k] += hv * __ldg(&Wb[(half * 7 + k) * HSZ + i]);
            }
        }
        #pragma unroll
        for (int k = 0; k < 7; k++) {
            #pragma unroll
            for (int o = 16; o; o >>= 1) acc[k] += __shfl_xor_sync(0xffffffffu, acc[k], o);
        }
        if (lane == 0) {
            #pragma unroll
            for (int k = 0; k < 7; k++)
                dst[(b * CLSK + half * 7 + k) * NN + m] = acc[k];
        }
    }
}

// ---------------- stage 4: u = h1 @ bwT^T. 64x64 tiles, 128 thr, 3-stage cp.async ----------------
__global__ void u_kernel()
{
    __shared__ unsigned As[3][64][20];
    __shared__ unsigned Bs[3][64][20];

    const int bk = blockIdx.z;
    const int b = bk / CLSK, kcls = bk % CLSK;
    const int m0 = blockIdx.x * 64;
    const int n0 = blockIdx.y * 64;
    const float* A  = g_h1 + b * NN * DP;
    const float* Bm = g_bwT + kcls * DP * DP;
    const int tid = threadIdx.x;
    const int w = tid >> 5, lane = tid & 31, g = lane >> 2, tig = lane & 3;
    const int wm = (w >> 1) * 32, wn = (w & 1) * 32;

    float acc[2][4][4] = {};

    #define U_STAGE(buf, k0)                                                     \
        do { _Pragma("unroll")                                                   \
        for (int h = 0; h < 2; h++) {                                            \
            int f = tid + h * 128;                                               \
            int r = f >> 2, kq = (f & 3) * 4;                                    \
            cp16(&As[buf][r][kq], &A[(m0 + r) * DP + (k0) + kq]);                \
            cp16(&Bs[buf][r][kq], &Bm[(n0 + r) * DP + (k0) + kq]);               \
        } } while (0)

    U_STAGE(0, 0);  CP_COMMIT();
    U_STAGE(1, 16); CP_COMMIT();

    const int NT = DP / 16;  // 17
    int cur = 0;
    for (int kt = 0; kt < NT; kt++) {
        if (kt + 1 < NT) CP_WAIT(1); else CP_WAIT(0);
        __syncthreads();
        if (kt + 2 < NT) {
            int nxt = cur + 2; if (nxt >= 3) nxt -= 3;
            U_STAGE(nxt, (kt + 2) * 16);
            CP_COMMIT();
        }
        #pragma unroll
        for (int kk = 0; kk < 2; kk++) {
            unsigned a[2][4], b2[4][2];
            #pragma unroll
            for (int i = 0; i < 2; i++) {
                a[i][0] = As[cur][wm + i * 16 + g][kk * 8 + tig];
                a[i][1] = As[cur][wm + i * 16 + g + 8][kk * 8 + tig];
                a[i][2] = As[cur][wm + i * 16 + g][kk * 8 + tig + 4];
                a[i][3] = As[cur][wm + i * 16 + g + 8][kk * 8 + tig + 4];
            }
            #pragma unroll
            for (int j = 0; j < 4; j++) {
                b2[j][0] = Bs[cur][wn + j * 8 + g][kk * 8 + tig];
                b2[j][1] = Bs[cur][wn + j * 8 + g][kk * 8 + tig + 4];
            }
            #pragma unroll
            for (int i = 0; i < 2; i++)
                #pragma unroll
                for (int j = 0; j < 4; j++) mma8(acc[i][j], a[i], b2[j]);
        }
        if (++cur == 3) cur = 0;
    }

    float* U = g_u + bk * NN * DP;
    #pragma unroll
    for (int i = 0; i < 2; i++) {
        #pragma unroll
        for (int rh = 0; rh < 2; rh++) {
            int m = m0 + wm + i * 16 + g + rh * 8;
            #pragma unroll
            for (int j = 0; j < 4; j++) {
                int c = n0 + wn + j * 8 + tig * 2;
                if (c + 1 < DP) {
                    float2 vv = make_float2(f2tf(acc[i][j][rh * 2 + 0]),
                                            f2tf(acc[i][j][rh * 2 + 1]));
                    *(float2*)&U[m * DP + c] = vv;
                }
            }
        }
    }
}

// ---------------- stage 5: out = u @ t1^T + biases. 128x128 tiles, 256 thr, 3-stage cp.async ----------------
#define O_TILE_U (128 * 20)
__global__ void out_kernel(float* __restrict__ out)
{
    extern __shared__ unsigned dyn[];
    unsigned (*As)[128][20] = (unsigned(*)[128][20])dyn;
    unsigned (*Bs)[128][20] = (unsigned(*)[128][20])(dyn + 3 * O_TILE_U);
    __shared__ float sHW[128], sTW[128], sSB[NPOS];

    const int bk = blockIdx.z;
    const int b = bk / CLSK, kcls = bk % CLSK;
    const int m0 = blockIdx.x * 128;
    const int n0 = blockIdx.y * 128;
    const float* A  = g_u + bk * NN * DP;
    const float* Bt = g_t1 + b * NN * DP;
    const int tid = threadIdx.x;
    const int w = tid >> 5, lane = tid & 31, g = lane >> 2, tig = lane & 3;
    const int wm = (w >> 1) * 32, wn = (w & 1) * 64;

    if (tid < 128) {
        sHW[tid] = g_headW[bk * NN + m0 + tid];
        sTW[tid] = g_tailW[bk * NN + n0 + tid];
    }
    if (tid < NPOS) sSB[tid] = g_sbias[kcls * NPOS + tid];

    float acc[2][8][4] = {};

    #define O_STAGE(buf, k0)                                                     \
        do { _Pragma("unroll")                                                   \
        for (int h = 0; h < 2; h++) {                                            \
            int f = tid + h * 256;                                               \
            int r = f >> 2, kq = (f & 3) * 4;                                    \
            cp16(&As[buf][r][kq], &A[(m0 + r) * DP + (k0) + kq]);                \
            cp16(&Bs[buf][r][kq], &Bt[(n0 + r) * DP + (k0) + kq]);               \
        } } while (0)

    O_STAGE(0, 0);  CP_COMMIT();
    O_STAGE(1, 16); CP_COMMIT();

    const int NT = DP / 16;  // 17
    int cur = 0;
    for (int kt = 0; kt < NT; kt++) {
        if (kt + 1 < NT) CP_WAIT(1); else CP_WAIT(0);
        __syncthreads();
        if (kt + 2 < NT) {
            int nxt = cur + 2; if (nxt >= 3) nxt -= 3;
            O_STAGE(nxt, (kt + 2) * 16);
            CP_COMMIT();
        }
        #pragma unroll
        for (int kk = 0; kk < 2; kk++) {
            unsigned a[2][4], b2[8][2];
            #pragma unroll
            for (int i = 0; i < 2; i++) {
                a[i][0] = As[cur][wm + i * 16 + g][kk * 8 + tig];
                a[i][1] = As[cur][wm + i * 16 + g + 8][kk * 8 + tig];
                a[i][2] = As[cur][wm + i * 16 + g][kk * 8 + tig + 4];
                a[i][3] = As[cur][wm + i * 16 + g + 8][kk * 8 + tig + 4];
            }
            #pragma unroll
            for (int j = 0; j < 8; j++) {
                b2[j][0] = Bs[cur][wn + j * 8 + g][kk * 8 + tig];
                b2[j][1] = Bs[cur][wn + j * 8 + g][kk * 8 + tig + 4];
            }
            #pragma unroll
            for (int i = 0; i < 2; i++)
                #pragma unroll
                for (int j = 0; j < 8; j++) mma8(acc[i][j], a[i], b2[j]);
        }
        if (++cur == 3) cur = 0;
    }

    #pragma unroll
    for (int i = 0; i < 2; i++) {
        #pragma unroll
        for (int rh = 0; rh < 2; rh++) {
            int ml = wm + i * 16 + g + rh * 8;
            int m = m0 + ml;
            float hv = sHW[ml];
            #pragma unroll
            for (int j = 0; j < 8; j++) {
                int cl = wn + j * 8 + tig * 2;
                int n = n0 + cl;
                int d0 = n - m;     d0 = (d0 < -15) ? -15 : (d0 > 14 ? 14 : d0);
                int d1 = n + 1 - m; d1 = (d1 < -15) ? -15 : (d1 > 14 ? 14 : d1);
                float2 vv;
                vv.x = acc[i][j][rh * 2 + 0] + hv + sTW[cl]     + sSB[d0 + 15];
                vv.y = acc[i][j][rh * 2 + 1] + hv + sTW[cl + 1] + sSB[d1 + 15];
                *(float2*)&out[(bk * NN + m) * NN + n] = vv;
            }
        }
    }
}

// ---------------- launch ----------------
extern "C" void kernel_launch(void* const* d_in, const int* in_sizes, int n_in,
                              void* d_out, int out_size)
{
    const float* x   = (const float*)d_in[0];
    const float* y   = (const float*)d_in[1];
    // d_in[2] = z : dead input
    const float* w1  = (const float*)d_in[3];
    const float* b1  = (const float*)d_in[4];
    const float* w2  = (const float*)d_in[5];
    const float* b2  = (const float*)d_in[6];
    const float* hw  = (const float*)d_in[7];
    const float* hb  = (const float*)d_in[8];
    const float* tw  = (const float*)d_in[9];
    const float* tb  = (const float*)d_in[10];
    const float* bw  = (const float*)d_in[11];
    const float* W   = (const float*)d_in[12];
    const float* se  = (const float*)d_in[13];
    float* out = (float*)d_out;

    const int OUT_SMEM = 3 * 2 * O_TILE_U * 4;   // 61440 bytes
    static int attr_done = 0;
    if (!attr_done) {
        cudaFuncSetAttribute(out_kernel, cudaFuncAttributeMaxDynamicSharedMemorySize, OUT_SMEM);
        attr_done = 1;
    }

    prep_kernel<<<TR_BLOCKS + 5, 256>>>(bw, W, se);
    proj_kernel<<<dim3(16, 4, 4), 128>>>(x, y, w1, b1, w2, b2, hw, hb, tw, tb);
    hw_kernel<<<256, 256>>>(W);
    u_kernel<<<dim3(8, 5, BB * CLSK), 128>>>();
    out_kernel<<<dim3(4, 4, BB * CLSK), 256, OUT_SMEM>>>(out);
}